// round 2
// baseline (speedup 1.0000x reference)
#include <cuda_runtime.h>
#include <cuda_bf16.h>

// Problem constants (match reference)
#define WPIX 512.0f
#define HPIX 512.0f
#define S_MIN (1.0f / 30.0f)
#define S_MAX (1.0f / 0.75f)
#define MU_BORDER 1.05f
#define PI_APPROX 3.1416f

#define MAX_N 1024  // static scratch sizing; actual N = 512

// Per-gaussian precomputed data:
// g_ga[n] = (gm.x, gm.y, Sx, Sy)   gm = tanh(mu)*1.05*(wh/2)
// g_gb[n] = (cos(a), sin(a), sigmoid(opacity), 0)
// g_sh[n*7 + j] = repacked rgbsh (27 floats + pad), row-major (m, ch)
__device__ float4 g_ga[MAX_N];
__device__ float4 g_gb[MAX_N];
__device__ float4 g_sh[MAX_N * 7];

__global__ void precompute_kernel(const float* __restrict__ rgbsh,
                                  const float* __restrict__ opacity,
                                  const float* __restrict__ mu,
                                  const float* __restrict__ scale,
                                  const float* __restrict__ angle,
                                  int N) {
    int n = blockIdx.x * blockDim.x + threadIdx.x;
    if (n >= N) return;

    float gmx = tanhf(mu[2 * n + 0]) * (MU_BORDER * WPIX * 0.5f);
    float gmy = tanhf(mu[2 * n + 1]) * (MU_BORDER * HPIX * 0.5f);
    float sx = fminf(fmaxf(scale[2 * n + 0], 0.0f), 1.0f) * (S_MAX - S_MIN) + S_MIN;
    float sy = fminf(fmaxf(scale[2 * n + 1], 0.0f), 1.0f) * (S_MAX - S_MIN) + S_MIN;
    g_ga[n] = make_float4(gmx, gmy, sx, sy);

    float alpha = tanhf(angle[n]) * PI_APPROX;
    float c, s;
    sincosf(alpha, &s, &c);
    float op = 1.0f / (1.0f + expf(-opacity[n]));
    g_gb[n] = make_float4(c, s, op, 0.0f);

    // repack 27 SH coeffs into 7 float4
    float v[28];
#pragma unroll
    for (int m = 0; m < 27; ++m) v[m] = rgbsh[n * 27 + m];
    v[27] = 0.0f;
#pragma unroll
    for (int j = 0; j < 7; ++j)
        g_sh[n * 7 + j] = make_float4(v[4 * j], v[4 * j + 1], v[4 * j + 2], v[4 * j + 3]);
}

// Main kernel: 512 threads/block. Threads (tid & 255) index 256 rays per block;
// slice = tid >> 8 in {0,1} splits the gaussian list. Smem reduce at the end.
#define RAYS_PER_BLOCK 256
#define SLICES 2
#define THREADS (RAYS_PER_BLOCK * SLICES)

__global__ __launch_bounds__(THREADS, 1)
void splat_kernel(const float* __restrict__ x,
                  float* __restrict__ out,
                  int B, int N) {
    __shared__ float redR[THREADS];
    __shared__ float redG[THREADS];
    __shared__ float redB[THREADS];

    int tid = threadIdx.x;
    int rayLocal = tid & (RAYS_PER_BLOCK - 1);
    int slice = tid >> 8;  // 0 or 1
    int ray = blockIdx.x * RAYS_PER_BLOCK + rayLocal;

    float sumR = 0.0f, sumG = 0.0f, sumB = 0.0f;

    if (ray < B) {
        // vec = x - wh/2 - gm  (exact algebraic reduction of the reference)
        float px = x[2 * ray + 0] - (WPIX * 0.5f);
        float py = x[2 * ray + 1] - (HPIX * 0.5f);

        int per = (N + SLICES - 1) / SLICES;
        int n0 = slice * per;
        int n1 = min(n0 + per, N);

#pragma unroll 4
        for (int n = n0; n < n1; ++n) {
            float4 ga = g_ga[n];
            float vx = px - ga.x;
            float vy = py - ga.y;
            float svx = vx * ga.z;
            float svy = vy * ga.w;
            float d2 = fmaf(svx, svx, svy * svy);
            if (d2 < 25.0f) {
                // --- heavy path: ~0.3% of pairs ---
                float4 gb = g_gb[n];
                float c = gb.x, s = gb.y;
                float w = __expf(-d2) * gb.z;

                // rotated (unscaled) direction; theta = atan2(rvx, rvy)
                float rvx = c * vx - s * vy;
                float rvy = fmaf(s, vx, c * vy);
                float rn = rsqrtf(fmaf(rvx, rvx, fmaf(rvy, rvy, 1e-20f)));
                float s1 = rvx * rn;   // sin(theta)
                float c1 = rvy * rn;   // cos(theta)
                // harmonics via angle addition
                float s2 = 2.0f * s1 * c1;
                float c2 = fmaf(c1, c1, -s1 * s1);
                float s3 = fmaf(s1, c2, c1 * s2);
                float c3 = fmaf(c1, c2, -s1 * s2);
                float s4 = 2.0f * s2 * c2;
                float c4 = fmaf(c2, c2, -s2 * s2);

                const float4* shp = &g_sh[n * 7];
                float4 q0 = shp[0], q1 = shp[1], q2 = shp[2], q3 = shp[3];
                float4 q4 = shp[4], q5 = shp[5], q6 = shp[6];

                // channel R: m = 0,3,6,...,24
                float aR = q0.x;
                aR = fmaf(s1, q0.w, aR); aR = fmaf(c1, q1.z, aR);
                aR = fmaf(s2, q2.y, aR); aR = fmaf(c2, q3.x, aR);
                aR = fmaf(s3, q3.w, aR); aR = fmaf(c3, q4.z, aR);
                aR = fmaf(s4, q5.y, aR); aR = fmaf(c4, q6.x, aR);
                // channel G
                float aG = q0.y;
                aG = fmaf(s1, q1.x, aG); aG = fmaf(c1, q1.w, aG);
                aG = fmaf(s2, q2.z, aG); aG = fmaf(c2, q3.y, aG);
                aG = fmaf(s3, q4.x, aG); aG = fmaf(c3, q4.w, aG);
                aG = fmaf(s4, q5.z, aG); aG = fmaf(c4, q6.y, aG);
                // channel B
                float aB = q0.z;
                aB = fmaf(s1, q1.y, aB); aB = fmaf(c1, q2.x, aB);
                aB = fmaf(s2, q2.w, aB); aB = fmaf(c2, q3.z, aB);
                aB = fmaf(s3, q4.y, aB); aB = fmaf(c3, q5.x, aB);
                aB = fmaf(s4, q5.w, aB); aB = fmaf(c4, q6.z, aB);

                // sigmoid per channel, weighted accumulate
                float rR = __fdividef(1.0f, 1.0f + __expf(-aR));
                float rG = __fdividef(1.0f, 1.0f + __expf(-aG));
                float rB = __fdividef(1.0f, 1.0f + __expf(-aB));
                sumR = fmaf(w, rR, sumR);
                sumG = fmaf(w, rG, sumG);
                sumB = fmaf(w, rB, sumB);
            }
        }
    }

    redR[tid] = sumR;
    redG[tid] = sumG;
    redB[tid] = sumB;
    __syncthreads();

    if (tid < RAYS_PER_BLOCK) {
        int ray2 = blockIdx.x * RAYS_PER_BLOCK + tid;
        if (ray2 < B) {
            float r = redR[tid] + redR[tid + RAYS_PER_BLOCK];
            float g = redG[tid] + redG[tid + RAYS_PER_BLOCK];
            float b = redB[tid] + redB[tid + RAYS_PER_BLOCK];
            out[3 * ray2 + 0] = r;
            out[3 * ray2 + 1] = g;
            out[3 * ray2 + 2] = b;
        }
    }
}

extern "C" void kernel_launch(void* const* d_in, const int* in_sizes, int n_in,
                              void* d_out, int out_size) {
    // metadata order: x, rgbsh, opacity, mu, scale, angle
    const float* x       = (const float*)d_in[0];
    const float* rgbsh   = (const float*)d_in[1];
    const float* opacity = (const float*)d_in[2];
    const float* mu      = (const float*)d_in[3];
    const float* scale   = (const float*)d_in[4];
    const float* angle   = (const float*)d_in[5];
    float* out = (float*)d_out;

    int B = in_sizes[0] / 2;
    int N = in_sizes[2];

    precompute_kernel<<<(N + 255) / 256, 256>>>(rgbsh, opacity, mu, scale, angle, N);

    int grid = (B + RAYS_PER_BLOCK - 1) / RAYS_PER_BLOCK;
    splat_kernel<<<grid, THREADS>>>(x, out, B, N);
}